// round 5
// baseline (speedup 1.0000x reference)
#include <cuda_runtime.h>
#include <math.h>

#define SCALE 64.0f
#define MARGIN 0.35f

// Output layout (f32, flattened tuple in reference order):
//   [0, B*(C-1))            diff_logits, row-major
//   [B*(C-1), +B)           sin_theta
//   [+B, +2B)               sin_theta_plus_m
//   [+2B, +3B)              sin_m
//
// Labels dtype sniff: reference uses int64, but the harness may materialize
// int32. For int64 little-endian labels in [0, 100000) every odd 32-bit word
// is 0; for an int32 label array those words are random labels (zero w.p.
// 1e-5 each). Checking 8 odd words disambiguates deterministically.
__device__ __forceinline__ int load_label(const int* labels32, int row) {
    bool is_i64 = true;
#pragma unroll
    for (int k = 1; k <= 15; k += 2) is_i64 &= (labels32[k] == 0);
    return is_i64 ? labels32[2 * row] : labels32[row];
}

__global__ void cosface_kernel(const float* __restrict__ logits,
                               const int* __restrict__ labels32,
                               float* __restrict__ out,
                               int B, int C) {
    const int row = blockIdx.y;
    const int Cm1 = C - 1;
    const int label = load_label(labels32, row);

    const float* __restrict__ lrow = logits + (size_t)row * (size_t)C;
    float* __restrict__ orow = out + (size_t)row * (size_t)Cm1;

    const float target = __ldg(lrow + label);       // broadcast; keep cached
    const float ft = target - MARGIN;               // final_target_logit

    const int stride = gridDim.x * blockDim.x;
    for (int j = blockIdx.x * blockDim.x + threadIdx.x; j < Cm1; j += stride) {
        const int src = j + (j >= label);
        const float v = __ldcs(lrow + src);         // streaming load (evict-first)
        __stcs(orow + j, SCALE * (v - ft));         // streaming store
    }

    if (blockIdx.x == 0 && threadIdx.x == 0) {
        // sin(acos(x)) == sqrt(1 - x^2) on [0,1): cheaper and tighter ulp.
        const float sin_t  = sqrtf(fmaxf(0.0f, 1.0f - target * target));
        const float sin_tm = sqrtf(fmaxf(0.0f, 1.0f - ft * ft));
        const float theta   = acosf(target);
        const float theta_m = acosf(ft);
        const size_t base = (size_t)B * (size_t)Cm1;
        out[base + row]           = sin_t;
        out[base + B + row]       = sin_tm;
        out[base + 2 * B + row]   = sinf(theta_m - theta);
    }
}

extern "C" void kernel_launch(void* const* d_in, const int* in_sizes, int n_in,
                              void* d_out, int out_size) {
    const float* logits = (const float*)d_in[0];
    const int* labels32 = (const int*)d_in[1];
    float* out = (float*)d_out;

    const int B = in_sizes[1];              // 512
    const int C = in_sizes[0] / B;          // 100000

    dim3 block(256);
    dim3 grid(49, B);                       // ~8 grid-stride iters/thread
    cosface_kernel<<<grid, block>>>(logits, labels32, out, B, C);
}

// round 8
// speedup vs baseline: 1.7941x; 1.7941x over previous
#include <cuda_runtime.h>
#include <math.h>

#define SCALE 64.0f
#define MARGIN 0.35f
#define UNROLL 8
#define TPB 256

// Output layout (f32, flattened tuple in reference order):
//   [0, B*(C-1))            diff_logits, row-major
//   [B*(C-1), +B)           sin_theta
//   [+B, +2B)               sin_theta_plus_m
//   [+2B, +3B)              sin_m
//
// Labels dtype sniff: harness materializes int64 labels; for LE int64 in
// [0, 100000) every odd 32-bit word is 0. Checking 8 odd words distinguishes
// int64 (stride-2 read) from a plain int32 array deterministically.
__device__ __forceinline__ int load_label(const int* labels32, int row) {
    bool is_i64 = true;
#pragma unroll
    for (int k = 1; k <= 15; k += 2) is_i64 &= (labels32[k] == 0);
    return is_i64 ? labels32[2 * row] : labels32[row];
}

__global__ void cosface_kernel(const float* __restrict__ logits,
                               const int* __restrict__ labels32,
                               float* __restrict__ out,
                               int B, int C) {
    const int row = blockIdx.y;
    const int Cm1 = C - 1;
    const int label = load_label(labels32, row);

    const float* __restrict__ lrow = logits + (size_t)row * (size_t)C;
    float* __restrict__ orow = out + (size_t)row * (size_t)Cm1;

    const float target = __ldg(lrow + label);
    const float ft = target - MARGIN;               // final_target_logit

    // Contiguous 2048-col chunk per block; 8 front-batched independent loads
    // per thread (MLP_p1 = 8); each warp access is a coalesced 128B transaction.
    const int base = blockIdx.x * (TPB * UNROLL) + threadIdx.x;
    const bool full = (base + (UNROLL - 1) * TPB) < Cm1;   // all 8 in range

    float v[UNROLL];
    if (full) {
        // Fast path (48 of 49 chunks): unguarded batched loads.
#pragma unroll
        for (int u = 0; u < UNROLL; u++) {
            const int j = base + u * TPB;
            v[u] = __ldcs(lrow + j + (j >= label));
        }
#pragma unroll
        for (int u = 0; u < UNROLL; u++)
            __stcs(orow + base + u * TPB, SCALE * (v[u] - ft));
    } else {
#pragma unroll
        for (int u = 0; u < UNROLL; u++) {
            const int j = base + u * TPB;
            if (j < Cm1) v[u] = __ldcs(lrow + j + (j >= label));
        }
#pragma unroll
        for (int u = 0; u < UNROLL; u++) {
            const int j = base + u * TPB;
            if (j < Cm1) __stcs(orow + j, SCALE * (v[u] - ft));
        }
    }

    if (blockIdx.x == 0 && threadIdx.x == 0) {
        // sin(acos(x)) == sqrt(1 - x^2) on [0,1)
        const float sin_t  = sqrtf(fmaxf(0.0f, 1.0f - target * target));
        const float sin_tm = sqrtf(fmaxf(0.0f, 1.0f - ft * ft));
        const float theta   = acosf(target);
        const float theta_m = acosf(ft);
        const size_t sbase = (size_t)B * (size_t)Cm1;
        out[sbase + row]           = sin_t;
        out[sbase + B + row]       = sin_tm;
        out[sbase + 2 * B + row]   = sinf(theta_m - theta);
    }
}

extern "C" void kernel_launch(void* const* d_in, const int* in_sizes, int n_in,
                              void* d_out, int out_size) {
    const float* logits = (const float*)d_in[0];
    const int* labels32 = (const int*)d_in[1];
    float* out = (float*)d_out;

    const int B = in_sizes[1];              // 512
    const int C = in_sizes[0] / B;          // 100000

    dim3 block(TPB);
    dim3 grid((C - 1 + TPB * UNROLL - 1) / (TPB * UNROLL), B);   // (49, 512)
    cosface_kernel<<<grid, block>>>(logits, labels32, out, B, C);
}

// round 9
// speedup vs baseline: 1.8942x; 1.0558x over previous
#include <cuda_runtime.h>
#include <math.h>

#define SCALE 64.0f
#define MARGIN 0.35f
#define TPB 256
#define GROUPS 4            // float4 groups per thread -> 16 elements/thread
#define TILE (TPB * GROUPS * 4)

// Output layout (f32, flattened tuple in reference order):
//   [0, B*(C-1))            diff_logits, row-major
//   [B*(C-1), +B)           sin_theta
//   [+B, +2B)               sin_theta_plus_m
//   [+2B, +3B)              sin_m
//
// Labels dtype sniff: for LE int64 labels in [0, 100000) every odd 32-bit
// word is 0; for int32 labels those words are random. 8 odd words decide.
__device__ __forceinline__ bool labels_are_i64(const int* labels32) {
    bool is_i64 = true;
#pragma unroll
    for (int k = 1; k <= 15; k += 2) is_i64 &= (labels32[k] == 0);
    return is_i64;
}

__global__ void cosface_kernel(const float* __restrict__ logits,
                               const int* __restrict__ labels32,
                               float* __restrict__ out,
                               int B, int C) {
    const int Cm1 = C - 1;
    const bool i64 = labels_are_i64(labels32);

    // Flat tile over diff_logits. Each block spans at most one row boundary.
    const int tb = blockIdx.x * TILE;
    const int r0 = tb / Cm1;                       // one division per block
    const int base0 = r0 * Cm1;                    // first out index of row r0
    const int b1 = base0 + Cm1;                    // first out index of row r0+1
    const int r1 = (r0 + 1 < B) ? r0 + 1 : r0;

    const int lab0 = i64 ? labels32[2 * r0] : labels32[r0];
    const int lab1 = i64 ? labels32[2 * r1] : labels32[r1];
    const size_t lbase0 = (size_t)r0 * (size_t)C;
    const size_t lbase1 = (size_t)r1 * (size_t)C;
    const float ft0 = __ldg(logits + lbase0 + lab0) - MARGIN;
    const float ft1 = __ldg(logits + lbase1 + lab1) - MARGIN;

    const int total4 = (B * Cm1) >> 2;             // B*(C-1) divisible by 4

    int idx4[GROUPS];
    bool ok[GROUPS];
    float v[GROUPS][4];

    // Front-batched loads: up to 16 independent streaming LDGs in flight.
#pragma unroll
    for (int g = 0; g < GROUPS; g++) {
        idx4[g] = (tb >> 2) + threadIdx.x + g * TPB;
        ok[g] = (idx4[g] < total4);
        if (ok[g]) {
            const int t0 = idx4[g] << 2;
#pragma unroll
            for (int e = 0; e < 4; e++) {
                const int t = t0 + e;
                const bool hi = (t >= b1);
                const int j = t - (hi ? b1 : base0);
                const int lab = hi ? lab1 : lab0;
                const size_t src = (hi ? lbase1 : lbase0) + j + (j >= lab);
                v[g][e] = __ldcs(logits + src);
            }
        }
    }

    // Aligned 16B streaming stores (no line splits).
    float4* __restrict__ out4 = reinterpret_cast<float4*>(out);
#pragma unroll
    for (int g = 0; g < GROUPS; g++) {
        if (ok[g]) {
            const int t0 = idx4[g] << 2;
            float4 o;
            o.x = SCALE * (v[g][0] - ((t0 + 0 >= b1) ? ft1 : ft0));
            o.y = SCALE * (v[g][1] - ((t0 + 1 >= b1) ? ft1 : ft0));
            o.z = SCALE * (v[g][2] - ((t0 + 2 >= b1) ? ft1 : ft0));
            o.w = SCALE * (v[g][3] - ((t0 + 3 >= b1) ? ft1 : ft0));
            __stcs(out4 + idx4[g], o);
        }
    }

    // Epilogue scalars: block 0 computes all B rows' sines.
    if (blockIdx.x == 0) {
        const size_t sbase = (size_t)B * (size_t)Cm1;
        for (int r = threadIdx.x; r < B; r += TPB) {
            const int lab = i64 ? labels32[2 * r] : labels32[r];
            const float tg = __ldg(logits + (size_t)r * (size_t)C + lab);
            const float ftv = tg - MARGIN;
            // sin(acos(x)) == sqrt(1 - x^2) on [0,1)
            out[sbase + r]          = sqrtf(fmaxf(0.0f, 1.0f - tg * tg));
            out[sbase + B + r]      = sqrtf(fmaxf(0.0f, 1.0f - ftv * ftv));
            out[sbase + 2 * B + r]  = sinf(acosf(ftv) - acosf(tg));
        }
    }
}

extern "C" void kernel_launch(void* const* d_in, const int* in_sizes, int n_in,
                              void* d_out, int out_size) {
    const float* logits = (const float*)d_in[0];
    const int* labels32 = (const int*)d_in[1];
    float* out = (float*)d_out;

    const int B = in_sizes[1];              // 512
    const int C = in_sizes[0] / B;          // 100000

    const long long total = (long long)B * (C - 1);
    const int nblocks = (int)((total + TILE - 1) / TILE);   // 3125
    cosface_kernel<<<nblocks, TPB>>>(logits, labels32, out, B, C);
}